// round 2
// baseline (speedup 1.0000x reference)
#include <cuda_runtime.h>
#include <math.h>

#define Nn   50000
#define Ee   800000
#define Ff   500
#define HIDD 64
#define Hh   4
#define HCc  16
#define Ccl  8
#define KHOPS 2
#define CSTc 1e-5f

// ---------------- device scratch (no allocations allowed) ----------------
__device__ float g_x[Nn * HIDD];        // relu(node_feat @ Wi + bi)
__device__ float g_Q[Nn * HIDD];        // 1+elu(x@Wq+bq)   [N,H,HC]
__device__ float g_K[Nn * HIDD];        // 1+elu(x@Wk+bk)   [N,H,HC]
__device__ float g_V[Nn * 32];          // x@Wv+bv          [N,H,C]
__device__ float g_M0[(size_t)Nn * 512];  // M ping  [N,H,HC,C]
__device__ float g_M1[(size_t)Nn * 512];  // M pong
__device__ float g_Kb[Nn * 64];         // propagated Kf buffer
__device__ float g_hidden[Nn * 32];     // accumulated hidden [N,H,C]
__device__ float g_deginv[Nn];
__device__ int   g_deg[Nn];
__device__ int   g_rowptr[Nn + 1];
__device__ int   g_fill[Nn];
__device__ int   g_src[Ee];             // CSR (by dst) list of source nodes
__device__ float g_tM[512];             // sum_n Kf (x) V
__device__ float g_tK[64];              // sum_n Kf
__device__ int   g_is32;                // edge_index is int32 (JAX x64 disabled)

// ---------------- dtype detection ----------------
// Reads the first E elements interpreted as int64. That is exactly E*8 = 6.4MB,
// which is within the buffer under EITHER dtype (int32 buffer = 2E*4 = 6.4MB).
// If the data is really int32, an int64 read combines two int32 indices and the
// high word is almost surely nonzero somewhere -> value >= Nn -> int32.
__global__ void detect_kernel(const long long* __restrict__ ei) {
    int e = blockIdx.x * blockDim.x + threadIdx.x;
    if (e >= Ee) return;
    long long v = ei[e];
    if (v < 0 || v >= (long long)Nn) atomicExch(&g_is32, 1);
}

// ---------------- init / graph structure ----------------
__global__ void zero_kernel() {
    int i = blockIdx.x * blockDim.x + threadIdx.x;
    if (i == 0) g_is32 = 0;
    if (i < Nn) { g_deg[i] = 0; g_fill[i] = 0; }
    if (i < 512) g_tM[i] = 0.f;
    if (i < 64)  g_tK[i] = 0.f;
}

__device__ __forceinline__ int load_edge(const void* ei, int which, int e) {
    if (g_is32) return ((const int*)ei)[which * Ee + e];
    return (int)((const long long*)ei)[which * Ee + e];
}

__global__ void deg_kernel(const void* __restrict__ ei) {
    int e = blockIdx.x * blockDim.x + threadIdx.x;
    if (e >= Ee) return;
    int c = load_edge(ei, 1, e);
    atomicAdd(&g_deg[c], 1);
}

__global__ void deginv_kernel() {
    int i = blockIdx.x * blockDim.x + threadIdx.x;
    if (i >= Nn) return;
    int d = g_deg[i];
    g_deginv[i] = d > 0 ? 1.0f / (float)d : 0.0f;
}

// single-block exclusive scan of g_deg -> g_rowptr
__global__ void scan_kernel() {
    __shared__ int wsum[32];
    __shared__ int s_carry;
    int t = threadIdx.x, lane = t & 31, w = t >> 5;
    if (t == 0) s_carry = 0;
    __syncthreads();
    for (int base = 0; base < Nn; base += 1024) {
        int i = base + t;
        int v = (i < Nn) ? g_deg[i] : 0;
        int x = v;
        #pragma unroll
        for (int o = 1; o < 32; o <<= 1) {
            int y = __shfl_up_sync(0xffffffffu, x, o);
            if (lane >= o) x += y;
        }
        if (lane == 31) wsum[w] = x;
        __syncthreads();
        if (w == 0) {
            int s = wsum[lane];
            #pragma unroll
            for (int o = 1; o < 32; o <<= 1) {
                int y = __shfl_up_sync(0xffffffffu, s, o);
                if (lane >= o) s += y;
            }
            wsum[lane] = s;
        }
        __syncthreads();
        int off = (w > 0) ? wsum[w - 1] : 0;
        int incl = x + off;
        int carry = s_carry;
        if (i < Nn) g_rowptr[i] = carry + incl - v;
        __syncthreads();
        if (t == 1023) s_carry = carry + incl;
        __syncthreads();
    }
    if (threadIdx.x == 0) g_rowptr[Nn] = s_carry;
}

__global__ void fill_kernel(const void* __restrict__ ei) {
    int e = blockIdx.x * blockDim.x + threadIdx.x;
    if (e >= Ee) return;
    int r = load_edge(ei, 0, e);
    int c = load_edge(ei, 1, e);
    int pos = g_rowptr[c] + atomicAdd(&g_fill[c], 1);
    g_src[pos] = r;
}

// ---------------- x = relu(A @ Wi + bi),  A:[N,500]  Wi:[500,64] ----------------
__global__ void gemm_x_kernel(const float* __restrict__ A,
                              const float* __restrict__ Wi,
                              const float* __restrict__ bi) {
    __shared__ float sA[64][65];   // [kk][row]
    __shared__ float sW[64][64];   // [kk][col]
    int t = threadIdx.x;
    int r0 = blockIdx.x * 64;
    int rq = t & 15;   // row quad (4 rows)
    int cq = t >> 4;   // col quad (4 cols)
    float acc[4][4] = {};
    for (int kc = 0; kc < Ff; kc += 64) {
        #pragma unroll
        for (int li = 0; li < 16; ++li) {
            int lin = t + li * 256;
            int kk = lin & 63, rr = lin >> 6;
            int r = r0 + rr, k = kc + kk;
            sA[kk][rr] = (r < Nn && k < Ff) ? A[(size_t)r * Ff + k] : 0.f;
        }
        #pragma unroll
        for (int li = 0; li < 16; ++li) {
            int lin = t + li * 256;
            int cc = lin & 63, kk = lin >> 6;
            int k = kc + kk;
            sW[kk][cc] = (k < Ff) ? Wi[k * HIDD + cc] : 0.f;
        }
        __syncthreads();
        #pragma unroll
        for (int kk = 0; kk < 64; ++kk) {
            float a0 = sA[kk][rq * 4 + 0];
            float a1 = sA[kk][rq * 4 + 1];
            float a2 = sA[kk][rq * 4 + 2];
            float a3 = sA[kk][rq * 4 + 3];
            float4 wv = *(const float4*)&sW[kk][cq * 4];
            acc[0][0] += a0 * wv.x; acc[0][1] += a0 * wv.y; acc[0][2] += a0 * wv.z; acc[0][3] += a0 * wv.w;
            acc[1][0] += a1 * wv.x; acc[1][1] += a1 * wv.y; acc[1][2] += a1 * wv.z; acc[1][3] += a1 * wv.w;
            acc[2][0] += a2 * wv.x; acc[2][1] += a2 * wv.y; acc[2][2] += a2 * wv.z; acc[2][3] += a2 * wv.w;
            acc[3][0] += a3 * wv.x; acc[3][1] += a3 * wv.y; acc[3][2] += a3 * wv.z; acc[3][3] += a3 * wv.w;
        }
        __syncthreads();
    }
    #pragma unroll
    for (int rr = 0; rr < 4; ++rr) {
        int r = r0 + rq * 4 + rr;
        if (r < Nn) {
            #pragma unroll
            for (int cc = 0; cc < 4; ++cc) {
                int c = cq * 4 + cc;
                g_x[r * HIDD + c] = fmaxf(acc[rr][cc] + bi[c], 0.f);
            }
        }
    }
}

// ---------------- Q/K/V projections (thread per (node, out-col)) ----------------
__global__ void qkv_kernel(const float* __restrict__ Wq, const float* __restrict__ bq,
                           const float* __restrict__ Wk, const float* __restrict__ bk,
                           const float* __restrict__ Wv, const float* __restrict__ bv) {
    int idx = blockIdx.x * blockDim.x + threadIdx.x;
    if (idx >= Nn * 160) return;
    int n = idx / 160;
    int oc = idx - n * 160;
    const float* xr = g_x + n * HIDD;
    if (oc < 64) {
        float acc = bq[oc];
        #pragma unroll 8
        for (int k = 0; k < HIDD; ++k) acc += xr[k] * Wq[k * 64 + oc];
        g_Q[n * 64 + oc] = acc > 0.f ? 1.f + acc : __expf(acc);
    } else if (oc < 128) {
        int c = oc - 64;
        float acc = bk[c];
        #pragma unroll 8
        for (int k = 0; k < HIDD; ++k) acc += xr[k] * Wk[k * 64 + c];
        g_K[n * 64 + c] = acc > 0.f ? 1.f + acc : __expf(acc);
    } else {
        int c = oc - 128;
        float acc = bv[c];
        #pragma unroll 8
        for (int k = 0; k < HIDD; ++k) acc += xr[k] * Wv[k * 32 + c];
        g_V[n * 32 + c] = acc;
    }
}

// ---------------- M0 = Kf (x) V ; hidden init ; teleport partial sums ----------------
__global__ void minit_kernel(const float* __restrict__ hopwise) {
    int t = threadIdx.x;                 // 512 threads: t = h*128 + i*8 + j
    int npb = (Nn + gridDim.x - 1) / gridDim.x;
    int n0 = blockIdx.x * npb;
    int n1 = min(n0 + npb, Nn);
    int kidx = t >> 3;                   // h*16+i  (0..63)
    int vidx = ((t >> 7) << 3) | (t & 7);// h*8+j   (0..31)
    float h0 = hopwise[0];
    float tm = 0.f, tk = 0.f;
    for (int n = n0; n < n1; ++n) {
        float kv = g_K[n * 64 + kidx];
        float vv = g_V[n * 32 + vidx];
        float m = kv * vv;
        g_M0[(size_t)n * 512 + t] = m;
        tm += m;
        if (t < 64) tk += g_K[n * 64 + t];
        if (t < 32) g_hidden[n * 32 + t] = g_V[n * 32 + t] * h0;
    }
    atomicAdd(&g_tM[t], tm);
    if (t < 64) atomicAdd(&g_tK[t], tk);
}

// ---------------- fused propagate + attention + hidden update ----------------
template <bool WRITE>
__global__ void prop_kernel(const float* __restrict__ Min, const float* __restrict__ Kin,
                            float* __restrict__ Mout, float* __restrict__ Kout,
                            const float* __restrict__ hopwise,
                            const float* __restrict__ headwise, int hop) {
    __shared__ float sM[512];
    __shared__ float sK[64];
    int n = blockIdx.x;
    int t = threadIdx.x;
    int beg = g_rowptr[n], end = g_rowptr[n + 1];
    float acc = 0.f, kacc = 0.f;
    int e = beg;
    for (; e + 1 < end; e += 2) {
        int s0 = g_src[e], s1 = g_src[e + 1];
        float w0 = g_deginv[s0], w1 = g_deginv[s1];
        acc += Min[(size_t)s0 * 512 + t] * w0 + Min[(size_t)s1 * 512 + t] * w1;
        if (t < 64) kacc += Kin[s0 * 64 + t] * w0 + Kin[s1 * 64 + t] * w1;
    }
    if (e < end) {
        int s0 = g_src[e];
        float w0 = g_deginv[s0];
        acc += Min[(size_t)s0 * 512 + t] * w0;
        if (t < 64) kacc += Kin[s0 * 64 + t] * w0;
    }
    sM[t] = acc;
    if (t < 64) sK[t] = kacc;
    if (WRITE) {
        Mout[(size_t)n * 512 + t] = acc;
        if (t < 64) Kout[n * 64 + t] = kacc;
    }
    __syncthreads();
    if (t < 32) {
        int h = t >> 3, j = t & 7;
        float num = 0.f, den = 0.f;
        #pragma unroll
        for (int i = 0; i < 16; ++i) {
            float q = g_Q[n * 64 + h * 16 + i];
            num += q * sM[h * 128 + i * 8 + j];
            den += q * sK[h * 16 + i];
        }
        // layerwise = softmax over heads of headwise[:, hop]
        float e0 = __expf(headwise[0 * KHOPS + hop]);
        float e1 = __expf(headwise[1 * KHOPS + hop]);
        float e2 = __expf(headwise[2 * KHOPS + hop]);
        float e3 = __expf(headwise[3 * KHOPS + hop]);
        float esum = e0 + e1 + e2 + e3;
        float lw = (h == 0 ? e0 : h == 1 ? e1 : h == 2 ? e2 : e3) / esum;
        float gamma = hopwise[hop + 1] * lw;
        g_hidden[n * 32 + t] += gamma * num / (den + CSTc);
    }
}

// ---------------- output projection + teleport term ----------------
__global__ void final_kernel(const float* __restrict__ Wo, const float* __restrict__ bo,
                             const float* __restrict__ teleport, float* __restrict__ out) {
    int idx = blockIdx.x * blockDim.x + threadIdx.x;  // n*8 + c
    if (idx >= Nn * 8) return;
    int n = idx >> 3, c = idx & 7;
    float acc = bo[c];
    #pragma unroll
    for (int t = 0; t < 32; ++t) acc += g_hidden[n * 32 + t] * Wo[t * 8 + c];
    const float invN = 1.0f / (float)Nn;
    float th = 0.f;
    #pragma unroll
    for (int h = 0; h < 4; ++h) {
        float num = 0.f, den = 0.f;
        #pragma unroll
        for (int i = 0; i < 16; ++i) {
            float q = g_Q[n * 64 + h * 16 + i];
            num += q * g_tM[h * 128 + i * 8 + c];
            den += q * g_tK[h * 16 + i];
        }
        th += (num * invN) / (den * invN + CSTc);
    }
    out[idx] = acc + teleport[0] * th;
}

// ---------------- launch ----------------
extern "C" void kernel_launch(void* const* d_in, const int* in_sizes, int n_in,
                              void* d_out, int out_size) {
    const float* node_feat = (const float*)d_in[0];
    const void*  ei        = d_in[1];           // int32 or int64, detected on device
    const float* Wi        = (const float*)d_in[2];
    const float* bi        = (const float*)d_in[3];
    const float* Wq        = (const float*)d_in[4];
    const float* bq        = (const float*)d_in[5];
    const float* Wk        = (const float*)d_in[6];
    const float* bk        = (const float*)d_in[7];
    const float* Wv        = (const float*)d_in[8];
    const float* bv        = (const float*)d_in[9];
    const float* Wo        = (const float*)d_in[10];
    const float* bo        = (const float*)d_in[11];
    const float* hopwise   = (const float*)d_in[12];
    const float* headwise  = (const float*)d_in[13];
    const float* teleport  = (const float*)d_in[14];
    float* out = (float*)d_out;

    float* g_M0p; cudaGetSymbolAddress((void**)&g_M0p, g_M0);
    float* g_M1p; cudaGetSymbolAddress((void**)&g_M1p, g_M1);
    float* g_Kp;  cudaGetSymbolAddress((void**)&g_Kp,  g_K);
    float* g_Kbp; cudaGetSymbolAddress((void**)&g_Kbp, g_Kb);

    zero_kernel<<<(Nn + 255) / 256, 256>>>();
    detect_kernel<<<(Ee + 255) / 256, 256>>>((const long long*)ei);
    deg_kernel<<<(Ee + 255) / 256, 256>>>(ei);
    deginv_kernel<<<(Nn + 255) / 256, 256>>>();
    scan_kernel<<<1, 1024>>>();
    fill_kernel<<<(Ee + 255) / 256, 256>>>(ei);

    gemm_x_kernel<<<(Nn + 63) / 64, 256>>>(node_feat, Wi, bi);
    qkv_kernel<<<(Nn * 160 + 255) / 256, 256>>>(Wq, bq, Wk, bk, Wv, bv);
    minit_kernel<<<512, 512>>>(hopwise);

    // hop 0: M0 -> M1 (written), Kf -> Kb (written), hidden update
    prop_kernel<true><<<Nn, 512>>>(g_M0p, g_Kp, g_M1p, g_Kbp, hopwise, headwise, 0);
    // hop 1 (last): read M1/Kb, no writeback needed
    prop_kernel<false><<<Nn, 512>>>(g_M1p, g_Kbp, nullptr, nullptr, hopwise, headwise, 1);

    final_kernel<<<(Nn * 8 + 255) / 256, 256>>>(Wo, bo, teleport, out);
}

// round 3
// speedup vs baseline: 2.1495x; 2.1495x over previous
#include <cuda_runtime.h>
#include <cuda_fp16.h>
#include <math.h>

#define Nn   50000
#define Ee   800000
#define Ff   500
#define HIDD 64
#define KHOPS 2
#define CSTc 1e-5f

// ---------------- device scratch (no allocations allowed) ----------------
__device__ float  g_x[Nn * HIDD];          // relu(node_feat @ Wi + bi)
__device__ float  g_Q[Nn * HIDD];          // 1+elu(x@Wq+bq)   [N,H,HC]
__device__ float  g_K[Nn * HIDD];          // 1+elu(x@Wk+bk)   [N,H,HC] fp32
__device__ float  g_V[Nn * 32];            // x@Wv+bv          [N,H,C]
__device__ __half2 g_M0h[(size_t)Nn * 256]; // M ping  [N,H,HC,C] fp16 (51MB)
__device__ __half2 g_M1h[(size_t)Nn * 256]; // M pong (51MB)
__device__ __half  g_K16[Nn * 64];         // fp16 copy of Kf
__device__ __half  g_Kb16[Nn * 64];        // propagated Kf (fp16)
__device__ float  g_hidden[Nn * 32];       // accumulated hidden [N,H,C]
__device__ float  g_deginv[Nn];
__device__ int    g_deg[Nn];
__device__ int    g_rowptr[Nn + 1];
__device__ int    g_fill[Nn];
__device__ int    g_src[Ee];               // CSR (by dst) list of source nodes
__device__ float  g_tM[512];               // sum_n Kf (x) V
__device__ float  g_tK[64];                // sum_n Kf
__device__ int    g_is32 = 0;              // edge_index is int32 (sticky, deterministic)

// ---------------- dtype detection ----------------
__global__ void detect_kernel(const long long* __restrict__ ei) {
    int e = blockIdx.x * blockDim.x + threadIdx.x;
    if (e >= Ee) return;
    long long v = ei[e];
    if (v < 0 || v >= (long long)Nn) g_is32 = 1;
}

// ---------------- init / graph structure ----------------
__global__ void zero_kernel() {
    int i = blockIdx.x * blockDim.x + threadIdx.x;
    if (i < Nn) { g_deg[i] = 0; g_fill[i] = 0; }
    if (i < 512) g_tM[i] = 0.f;
    if (i < 64)  g_tK[i] = 0.f;
}

__device__ __forceinline__ int load_edge(const void* ei, int which, int e) {
    if (g_is32) return ((const int*)ei)[which * Ee + e];
    return (int)((const long long*)ei)[which * Ee + e];
}

__global__ void deg_kernel(const void* __restrict__ ei) {
    int e = blockIdx.x * blockDim.x + threadIdx.x;
    if (e >= Ee) return;
    atomicAdd(&g_deg[load_edge(ei, 1, e)], 1);
}

__global__ void deginv_kernel() {
    int i = blockIdx.x * blockDim.x + threadIdx.x;
    if (i >= Nn) return;
    int d = g_deg[i];
    g_deginv[i] = d > 0 ? 1.0f / (float)d : 0.0f;
}

// single-block exclusive scan of g_deg -> g_rowptr
__global__ void scan_kernel() {
    __shared__ int wsum[32];
    __shared__ int s_carry;
    int t = threadIdx.x, lane = t & 31, w = t >> 5;
    if (t == 0) s_carry = 0;
    __syncthreads();
    for (int base = 0; base < Nn; base += 1024) {
        int i = base + t;
        int v = (i < Nn) ? g_deg[i] : 0;
        int x = v;
        #pragma unroll
        for (int o = 1; o < 32; o <<= 1) {
            int y = __shfl_up_sync(0xffffffffu, x, o);
            if (lane >= o) x += y;
        }
        if (lane == 31) wsum[w] = x;
        __syncthreads();
        if (w == 0) {
            int s = wsum[lane];
            #pragma unroll
            for (int o = 1; o < 32; o <<= 1) {
                int y = __shfl_up_sync(0xffffffffu, s, o);
                if (lane >= o) s += y;
            }
            wsum[lane] = s;
        }
        __syncthreads();
        int off = (w > 0) ? wsum[w - 1] : 0;
        int incl = x + off;
        int carry = s_carry;
        if (i < Nn) g_rowptr[i] = carry + incl - v;
        __syncthreads();
        if (t == 1023) s_carry = carry + incl;
        __syncthreads();
    }
    if (threadIdx.x == 0) g_rowptr[Nn] = s_carry;
}

__global__ void fill_kernel(const void* __restrict__ ei) {
    int e = blockIdx.x * blockDim.x + threadIdx.x;
    if (e >= Ee) return;
    int r = load_edge(ei, 0, e);
    int c = load_edge(ei, 1, e);
    int pos = g_rowptr[c] + atomicAdd(&g_fill[c], 1);
    g_src[pos] = r;
}

// ---------------- x = relu(A @ Wi + bi),  A:[N,500]  Wi:[500,64] ----------------
__global__ void gemm_x_kernel(const float* __restrict__ A,
                              const float* __restrict__ Wi,
                              const float* __restrict__ bi) {
    __shared__ float sA[64][65];   // [kk][row]
    __shared__ float sW[64][64];   // [kk][col]
    int t = threadIdx.x;
    int r0 = blockIdx.x * 64;
    int rq = t & 15;
    int cq = t >> 4;
    float acc[4][4] = {};
    for (int kc = 0; kc < Ff; kc += 64) {
        #pragma unroll
        for (int li = 0; li < 16; ++li) {
            int lin = t + li * 256;
            int kk = lin & 63, rr = lin >> 6;
            int r = r0 + rr, k = kc + kk;
            sA[kk][rr] = (r < Nn && k < Ff) ? A[(size_t)r * Ff + k] : 0.f;
        }
        #pragma unroll
        for (int li = 0; li < 16; ++li) {
            int lin = t + li * 256;
            int cc = lin & 63, kk = lin >> 6;
            int k = kc + kk;
            sW[kk][cc] = (k < Ff) ? Wi[k * HIDD + cc] : 0.f;
        }
        __syncthreads();
        #pragma unroll
        for (int kk = 0; kk < 64; ++kk) {
            float a0 = sA[kk][rq * 4 + 0];
            float a1 = sA[kk][rq * 4 + 1];
            float a2 = sA[kk][rq * 4 + 2];
            float a3 = sA[kk][rq * 4 + 3];
            float4 wv = *(const float4*)&sW[kk][cq * 4];
            acc[0][0] += a0 * wv.x; acc[0][1] += a0 * wv.y; acc[0][2] += a0 * wv.z; acc[0][3] += a0 * wv.w;
            acc[1][0] += a1 * wv.x; acc[1][1] += a1 * wv.y; acc[1][2] += a1 * wv.z; acc[1][3] += a1 * wv.w;
            acc[2][0] += a2 * wv.x; acc[2][1] += a2 * wv.y; acc[2][2] += a2 * wv.z; acc[2][3] += a2 * wv.w;
            acc[3][0] += a3 * wv.x; acc[3][1] += a3 * wv.y; acc[3][2] += a3 * wv.z; acc[3][3] += a3 * wv.w;
        }
        __syncthreads();
    }
    #pragma unroll
    for (int rr = 0; rr < 4; ++rr) {
        int r = r0 + rq * 4 + rr;
        if (r < Nn) {
            #pragma unroll
            for (int cc = 0; cc < 4; ++cc) {
                int c = cq * 4 + cc;
                g_x[r * HIDD + c] = fmaxf(acc[rr][cc] + bi[c], 0.f);
            }
        }
    }
}

// ---------------- Q/K/V projections ----------------
__global__ void qkv_kernel(const float* __restrict__ Wq, const float* __restrict__ bq,
                           const float* __restrict__ Wk, const float* __restrict__ bk,
                           const float* __restrict__ Wv, const float* __restrict__ bv) {
    int idx = blockIdx.x * blockDim.x + threadIdx.x;
    if (idx >= Nn * 160) return;
    int n = idx / 160;
    int oc = idx - n * 160;
    const float* xr = g_x + n * HIDD;
    if (oc < 64) {
        float acc = bq[oc];
        #pragma unroll 8
        for (int k = 0; k < HIDD; ++k) acc += xr[k] * Wq[k * 64 + oc];
        g_Q[n * 64 + oc] = acc > 0.f ? 1.f + acc : __expf(acc);
    } else if (oc < 128) {
        int c = oc - 64;
        float acc = bk[c];
        #pragma unroll 8
        for (int k = 0; k < HIDD; ++k) acc += xr[k] * Wk[k * 64 + c];
        g_K[n * 64 + c] = acc > 0.f ? 1.f + acc : __expf(acc);
    } else {
        int c = oc - 128;
        float acc = bv[c];
        #pragma unroll 8
        for (int k = 0; k < HIDD; ++k) acc += xr[k] * Wv[k * 32 + c];
        g_V[n * 32 + c] = acc;
    }
}

// ---------------- M0 = Kf (x) V (fp16) ; hidden init ; teleport sums ; K16 copy ----------------
__global__ void minit_kernel(const float* __restrict__ hopwise) {
    int t = threadIdx.x;                  // 256 threads: half2 pair index
    int npb = (Nn + gridDim.x - 1) / gridDim.x;
    int n0 = blockIdx.x * npb;
    int n1 = min(n0 + npb, Nn);
    int kidx  = t >> 2;                   // (2t)>>3 = h*16+i (0..63)
    int vbase = ((t >> 6) << 3) | ((2 * t) & 7); // h*8 + j0 (even)
    float h0 = hopwise[0];
    float tm0 = 0.f, tm1 = 0.f, tk = 0.f;
    for (int n = n0; n < n1; ++n) {
        float kv = g_K[n * 64 + kidx];
        float2 vv = *(const float2*)&g_V[n * 32 + vbase];
        float m0 = kv * vv.x, m1 = kv * vv.y;
        g_M0h[(size_t)n * 256 + t] = __floats2half2_rn(m0, m1);
        tm0 += m0; tm1 += m1;
        if (t < 64) {
            float k = g_K[n * 64 + t];
            tk += k;
            g_K16[n * 64 + t] = __float2half_rn(k);
        }
        if (t < 32) g_hidden[n * 32 + t] = g_V[n * 32 + t] * h0;
    }
    atomicAdd(&g_tM[2 * t], tm0);
    atomicAdd(&g_tM[2 * t + 1], tm1);
    if (t < 64) atomicAdd(&g_tK[t], tk);
}

// ---------------- fused propagate + attention + hidden update (fp16 gather) ----------------
template <bool WRITE>
__global__ void prop_kernel(const __half2* __restrict__ Min, const __half2* __restrict__ Kin,
                            __half2* __restrict__ Mout, __half2* __restrict__ Kout,
                            const float* __restrict__ hopwise,
                            const float* __restrict__ headwise, int hop) {
    __shared__ float sM[512];
    __shared__ float sK[64];
    int n = blockIdx.x;
    int t = threadIdx.x;                  // 256
    int beg = g_rowptr[n], end = g_rowptr[n + 1];
    float accx = 0.f, accy = 0.f;
    float kx = 0.f, ky = 0.f;
    int e = beg;
    for (; e + 1 < end; e += 2) {
        int s0 = g_src[e], s1 = g_src[e + 1];
        float w0 = g_deginv[s0], w1 = g_deginv[s1];
        float2 m0 = __half22float2(Min[(size_t)s0 * 256 + t]);
        float2 m1 = __half22float2(Min[(size_t)s1 * 256 + t]);
        accx += m0.x * w0 + m1.x * w1;
        accy += m0.y * w0 + m1.y * w1;
        if (t < 32) {
            float2 k0 = __half22float2(Kin[s0 * 32 + t]);
            float2 k1 = __half22float2(Kin[s1 * 32 + t]);
            kx += k0.x * w0 + k1.x * w1;
            ky += k0.y * w0 + k1.y * w1;
        }
    }
    if (e < end) {
        int s0 = g_src[e];
        float w0 = g_deginv[s0];
        float2 m0 = __half22float2(Min[(size_t)s0 * 256 + t]);
        accx += m0.x * w0;
        accy += m0.y * w0;
        if (t < 32) {
            float2 k0 = __half22float2(Kin[s0 * 32 + t]);
            kx += k0.x * w0;
            ky += k0.y * w0;
        }
    }
    sM[2 * t]     = accx;
    sM[2 * t + 1] = accy;
    if (t < 32) { sK[2 * t] = kx; sK[2 * t + 1] = ky; }
    if (WRITE) {
        Mout[(size_t)n * 256 + t] = __floats2half2_rn(accx, accy);
        if (t < 32) Kout[n * 32 + t] = __floats2half2_rn(kx, ky);
    }
    __syncthreads();
    if (t < 32) {
        int h = t >> 3, j = t & 7;
        float num = 0.f, den = 0.f;
        #pragma unroll
        for (int i = 0; i < 16; ++i) {
            float q = g_Q[n * 64 + h * 16 + i];
            num += q * sM[h * 128 + i * 8 + j];
            den += q * sK[h * 16 + i];
        }
        float e0 = __expf(headwise[0 * KHOPS + hop]);
        float e1 = __expf(headwise[1 * KHOPS + hop]);
        float e2 = __expf(headwise[2 * KHOPS + hop]);
        float e3 = __expf(headwise[3 * KHOPS + hop]);
        float esum = e0 + e1 + e2 + e3;
        float lw = (h == 0 ? e0 : h == 1 ? e1 : h == 2 ? e2 : e3) / esum;
        float gamma = hopwise[hop + 1] * lw;
        g_hidden[n * 32 + t] += gamma * num / (den + CSTc);
    }
}

// ---------------- output projection + teleport term ----------------
__global__ void final_kernel(const float* __restrict__ Wo, const float* __restrict__ bo,
                             const float* __restrict__ teleport, float* __restrict__ out) {
    int idx = blockIdx.x * blockDim.x + threadIdx.x;  // n*8 + c
    if (idx >= Nn * 8) return;
    int n = idx >> 3, c = idx & 7;
    float acc = bo[c];
    #pragma unroll
    for (int t = 0; t < 32; ++t) acc += g_hidden[n * 32 + t] * Wo[t * 8 + c];
    const float invN = 1.0f / (float)Nn;
    float th = 0.f;
    #pragma unroll
    for (int h = 0; h < 4; ++h) {
        float num = 0.f, den = 0.f;
        #pragma unroll
        for (int i = 0; i < 16; ++i) {
            float q = g_Q[n * 64 + h * 16 + i];
            num += q * g_tM[h * 128 + i * 8 + c];
            den += q * g_tK[h * 16 + i];
        }
        th += (num * invN) / (den * invN + CSTc);
    }
    out[idx] = acc + teleport[0] * th;
}

// ---------------- launch ----------------
extern "C" void kernel_launch(void* const* d_in, const int* in_sizes, int n_in,
                              void* d_out, int out_size) {
    const float* node_feat = (const float*)d_in[0];
    const void*  ei        = d_in[1];           // int32 or int64, detected on device
    const float* Wi        = (const float*)d_in[2];
    const float* bi        = (const float*)d_in[3];
    const float* Wq        = (const float*)d_in[4];
    const float* bq        = (const float*)d_in[5];
    const float* Wk        = (const float*)d_in[6];
    const float* bk        = (const float*)d_in[7];
    const float* Wv        = (const float*)d_in[8];
    const float* bv        = (const float*)d_in[9];
    const float* Wo        = (const float*)d_in[10];
    const float* bo        = (const float*)d_in[11];
    const float* hopwise   = (const float*)d_in[12];
    const float* headwise  = (const float*)d_in[13];
    const float* teleport  = (const float*)d_in[14];
    float* out = (float*)d_out;

    __half2* M0p; cudaGetSymbolAddress((void**)&M0p, g_M0h);
    __half2* M1p; cudaGetSymbolAddress((void**)&M1p, g_M1h);
    __half*  K16p; cudaGetSymbolAddress((void**)&K16p, g_K16);
    __half*  Kb16p; cudaGetSymbolAddress((void**)&Kb16p, g_Kb16);

    zero_kernel<<<(Nn + 255) / 256, 256>>>();
    detect_kernel<<<(Ee + 255) / 256, 256>>>((const long long*)ei);
    deg_kernel<<<(Ee + 255) / 256, 256>>>(ei);
    deginv_kernel<<<(Nn + 255) / 256, 256>>>();
    scan_kernel<<<1, 1024>>>();
    fill_kernel<<<(Ee + 255) / 256, 256>>>(ei);

    gemm_x_kernel<<<(Nn + 63) / 64, 256>>>(node_feat, Wi, bi);
    qkv_kernel<<<(Nn * 160 + 255) / 256, 256>>>(Wq, bq, Wk, bk, Wv, bv);
    minit_kernel<<<512, 256>>>(hopwise);

    // hop 0: M0 -> M1 (written), K16 -> Kb16 (written), hidden update
    prop_kernel<true><<<Nn, 256>>>(M0p, (const __half2*)K16p, M1p, (__half2*)Kb16p,
                                   hopwise, headwise, 0);
    // hop 1 (last): read M1/Kb16, no writeback
    prop_kernel<false><<<Nn, 256>>>(M1p, (const __half2*)Kb16p, nullptr, nullptr,
                                    hopwise, headwise, 1);

    final_kernel<<<(Nn * 8 + 255) / 256, 256>>>(Wo, bo, teleport, out);
}

// round 4
// speedup vs baseline: 2.3094x; 1.0744x over previous
#include <cuda_runtime.h>
#include <cuda_fp16.h>
#include <math.h>

#define Nn   50000
#define Ee   800000
#define Ff   500
#define HIDD 64
#define KHOPS 2
#define CSTc 1e-5f

// ---------------- device scratch (no allocations allowed) ----------------
__device__ float  g_x[Nn * HIDD];          // relu(node_feat @ Wi + bi)
__device__ float  g_Q[Nn * HIDD];          // 1+elu(x@Wq+bq)   [N,H,HC]
__device__ float  g_K[Nn * HIDD];          // 1+elu(x@Wk+bk)   [N,H,HC] fp32
__device__ float  g_V[Nn * 32];            // x@Wv+bv          [N,H,C]  fp32
__device__ __half  g_K16[Nn * 64];         // fp16 Kf
__device__ __half  g_V16[Nn * 32];         // fp16 V
__device__ __half2 g_M1h[(size_t)Nn * 256]; // M after hop0 [N,H,HC,C] fp16 (51MB)
__device__ __half  g_Kb16[Nn * 64];        // propagated Kf (fp16)
__device__ float  g_hidden[Nn * 32];       // accumulated hidden [N,H,C]
__device__ float  g_deginv[Nn];
__device__ int    g_deg[Nn];
__device__ int    g_rowptr[Nn + 1];
__device__ int    g_fill[Nn];
__device__ int    g_src[Ee];               // CSR (by dst) list of source nodes
__device__ float  g_tM[512];               // sum_n Kf (x) V
__device__ float  g_tK[64];                // sum_n Kf
__device__ int    g_is32 = 0;

// ---------------- dtype detection ----------------
__global__ void detect_kernel(const long long* __restrict__ ei) {
    int e = blockIdx.x * blockDim.x + threadIdx.x;
    if (e >= Ee) return;
    long long v = ei[e];
    if (v < 0 || v >= (long long)Nn) g_is32 = 1;
}

// ---------------- init / graph structure ----------------
__global__ void zero_kernel() {
    int i = blockIdx.x * blockDim.x + threadIdx.x;
    if (i < Nn) { g_deg[i] = 0; g_fill[i] = 0; }
    if (i < 512) g_tM[i] = 0.f;
    if (i < 64)  g_tK[i] = 0.f;
}

__device__ __forceinline__ int load_edge(const void* ei, int which, int e) {
    if (g_is32) return ((const int*)ei)[which * Ee + e];
    return (int)((const long long*)ei)[which * Ee + e];
}

__global__ void deg_kernel(const void* __restrict__ ei) {
    int e = blockIdx.x * blockDim.x + threadIdx.x;
    if (e >= Ee) return;
    atomicAdd(&g_deg[load_edge(ei, 1, e)], 1);
}

__global__ void deginv_kernel() {
    int i = blockIdx.x * blockDim.x + threadIdx.x;
    if (i >= Nn) return;
    int d = g_deg[i];
    g_deginv[i] = d > 0 ? 1.0f / (float)d : 0.0f;
}

// single-block exclusive scan of g_deg -> g_rowptr
__global__ void scan_kernel() {
    __shared__ int wsum[32];
    __shared__ int s_carry;
    int t = threadIdx.x, lane = t & 31, w = t >> 5;
    if (t == 0) s_carry = 0;
    __syncthreads();
    for (int base = 0; base < Nn; base += 1024) {
        int i = base + t;
        int v = (i < Nn) ? g_deg[i] : 0;
        int x = v;
        #pragma unroll
        for (int o = 1; o < 32; o <<= 1) {
            int y = __shfl_up_sync(0xffffffffu, x, o);
            if (lane >= o) x += y;
        }
        if (lane == 31) wsum[w] = x;
        __syncthreads();
        if (w == 0) {
            int s = wsum[lane];
            #pragma unroll
            for (int o = 1; o < 32; o <<= 1) {
                int y = __shfl_up_sync(0xffffffffu, s, o);
                if (lane >= o) s += y;
            }
            wsum[lane] = s;
        }
        __syncthreads();
        int off = (w > 0) ? wsum[w - 1] : 0;
        int incl = x + off;
        int carry = s_carry;
        if (i < Nn) g_rowptr[i] = carry + incl - v;
        __syncthreads();
        if (t == 1023) s_carry = carry + incl;
        __syncthreads();
    }
    if (threadIdx.x == 0) g_rowptr[Nn] = s_carry;
}

__global__ void fill_kernel(const void* __restrict__ ei) {
    int e = blockIdx.x * blockDim.x + threadIdx.x;
    if (e >= Ee) return;
    int r = load_edge(ei, 0, e);
    int c = load_edge(ei, 1, e);
    int pos = g_rowptr[c] + atomicAdd(&g_fill[c], 1);
    g_src[pos] = r;
}

// ---------------- x = relu(A @ Wi + bi) ----------------
__global__ void gemm_x_kernel(const float* __restrict__ A,
                              const float* __restrict__ Wi,
                              const float* __restrict__ bi) {
    __shared__ float sA[64][65];
    __shared__ float sW[64][64];
    int t = threadIdx.x;
    int r0 = blockIdx.x * 64;
    int rq = t & 15;
    int cq = t >> 4;
    float acc[4][4] = {};
    for (int kc = 0; kc < Ff; kc += 64) {
        #pragma unroll
        for (int li = 0; li < 16; ++li) {
            int lin = t + li * 256;
            int kk = lin & 63, rr = lin >> 6;
            int r = r0 + rr, k = kc + kk;
            sA[kk][rr] = (r < Nn && k < Ff) ? A[(size_t)r * Ff + k] : 0.f;
        }
        #pragma unroll
        for (int li = 0; li < 16; ++li) {
            int lin = t + li * 256;
            int cc = lin & 63, kk = lin >> 6;
            int k = kc + kk;
            sW[kk][cc] = (k < Ff) ? Wi[k * HIDD + cc] : 0.f;
        }
        __syncthreads();
        #pragma unroll
        for (int kk = 0; kk < 64; ++kk) {
            float a0 = sA[kk][rq * 4 + 0];
            float a1 = sA[kk][rq * 4 + 1];
            float a2 = sA[kk][rq * 4 + 2];
            float a3 = sA[kk][rq * 4 + 3];
            float4 wv = *(const float4*)&sW[kk][cq * 4];
            acc[0][0] += a0 * wv.x; acc[0][1] += a0 * wv.y; acc[0][2] += a0 * wv.z; acc[0][3] += a0 * wv.w;
            acc[1][0] += a1 * wv.x; acc[1][1] += a1 * wv.y; acc[1][2] += a1 * wv.z; acc[1][3] += a1 * wv.w;
            acc[2][0] += a2 * wv.x; acc[2][1] += a2 * wv.y; acc[2][2] += a2 * wv.z; acc[2][3] += a2 * wv.w;
            acc[3][0] += a3 * wv.x; acc[3][1] += a3 * wv.y; acc[3][2] += a3 * wv.z; acc[3][3] += a3 * wv.w;
        }
        __syncthreads();
    }
    #pragma unroll
    for (int rr = 0; rr < 4; ++rr) {
        int r = r0 + rq * 4 + rr;
        if (r < Nn) {
            #pragma unroll
            for (int cc = 0; cc < 4; ++cc) {
                int c = cq * 4 + cc;
                g_x[r * HIDD + c] = fmaxf(acc[rr][cc] + bi[c], 0.f);
            }
        }
    }
}

// ---------------- Q/K/V projections ----------------
__global__ void qkv_kernel(const float* __restrict__ Wq, const float* __restrict__ bq,
                           const float* __restrict__ Wk, const float* __restrict__ bk,
                           const float* __restrict__ Wv, const float* __restrict__ bv) {
    int idx = blockIdx.x * blockDim.x + threadIdx.x;
    if (idx >= Nn * 160) return;
    int n = idx / 160;
    int oc = idx - n * 160;
    const float* xr = g_x + n * HIDD;
    if (oc < 64) {
        float acc = bq[oc];
        #pragma unroll 8
        for (int k = 0; k < HIDD; ++k) acc += xr[k] * Wq[k * 64 + oc];
        g_Q[n * 64 + oc] = acc > 0.f ? 1.f + acc : __expf(acc);
    } else if (oc < 128) {
        int c = oc - 64;
        float acc = bk[c];
        #pragma unroll 8
        for (int k = 0; k < HIDD; ++k) acc += xr[k] * Wk[k * 64 + c];
        g_K[n * 64 + c] = acc > 0.f ? 1.f + acc : __expf(acc);
    } else {
        int c = oc - 128;
        float acc = bv[c];
        #pragma unroll 8
        for (int k = 0; k < HIDD; ++k) acc += xr[k] * Wv[k * 32 + c];
        g_V[n * 32 + c] = acc;
    }
}

// ---------------- teleport sums ; hidden init ; fp16 copies of K,V ----------------
__global__ void minit_kernel(const float* __restrict__ hopwise) {
    int t = threadIdx.x;                  // 256 threads: M pair index (2t, 2t+1)
    int npb = (Nn + gridDim.x - 1) / gridDim.x;
    int n0 = blockIdx.x * npb;
    int n1 = min(n0 + npb, Nn);
    int kidx  = t >> 2;                   // h*16+i
    int vbase = ((t >> 6) << 3) | ((2 * t) & 7); // h*8 + j0 (even)
    float h0 = hopwise[0];
    float tm0 = 0.f, tm1 = 0.f, tk = 0.f;
    for (int n = n0; n < n1; ++n) {
        float kv = g_K[n * 64 + kidx];
        float2 vv = *(const float2*)&g_V[n * 32 + vbase];
        tm0 += kv * vv.x; tm1 += kv * vv.y;
        if (t < 64) {
            float k = g_K[n * 64 + t];
            tk += k;
            g_K16[n * 64 + t] = __float2half_rn(k);
        }
        if (t < 32) {
            float v = g_V[n * 32 + t];
            g_hidden[n * 32 + t] = v * h0;
            g_V16[n * 32 + t] = __float2half_rn(v);
        }
    }
    atomicAdd(&g_tM[2 * t], tm0);
    atomicAdd(&g_tM[2 * t + 1], tm1);
    if (t < 64) atomicAdd(&g_tK[t], tk);
}

// ---------------- hop 0: on-the-fly outer-product propagate + attention ----------------
#define CH 16
__global__ void hop0_kernel(const float* __restrict__ hopwise,
                            const float* __restrict__ headwise) {
    __shared__ __half2 sKe[CH][32];   // staged K rows (64 half)
    __shared__ __half2 sVe[CH][16];   // staged V rows (32 half)
    __shared__ float   swv[CH];
    __shared__ float   sM[512];
    __shared__ float   sKa[64];
    int n = blockIdx.x;
    int t = threadIdx.x;               // 256
    int beg = g_rowptr[n], end = g_rowptr[n + 1];
    int kidx = t >> 2;                 // h*16+i
    int vh2  = ((t >> 6) << 2) | (t & 3); // half2 index of V pair (j0,j0+1)
    float accx = 0.f, accy = 0.f, kx = 0.f, ky = 0.f;
    const __half2* K2 = (const __half2*)g_K16;
    const __half2* V2 = (const __half2*)g_V16;
    for (int c0 = beg; c0 < end; c0 += CH) {
        int ne = min(CH, end - c0);
        for (int idx = t; idx < ne * 48; idx += 256) {
            int e = idx / 48, off = idx - e * 48;
            int s = g_src[c0 + e];
            if (off < 32) sKe[e][off] = K2[s * 32 + off];
            else          sVe[e][off - 32] = V2[s * 16 + (off - 32)];
        }
        if (t < ne) swv[t] = g_deginv[g_src[c0 + t]];
        __syncthreads();
        for (int e = 0; e < ne; ++e) {
            float w = swv[e];
            float k = __half2float(((const __half*)sKe[e])[kidx]);
            float2 v = __half22float2(sVe[e][vh2]);
            float wk = w * k;
            accx += wk * v.x;
            accy += wk * v.y;
            if (t < 32) {
                float2 kk = __half22float2(sKe[e][t]);
                kx += w * kk.x;
                ky += w * kk.y;
            }
        }
        __syncthreads();
    }
    g_M1h[(size_t)n * 256 + t] = __floats2half2_rn(accx, accy);
    sM[2 * t] = accx; sM[2 * t + 1] = accy;
    if (t < 32) {
        ((__half2*)g_Kb16)[n * 32 + t] = __floats2half2_rn(kx, ky);
        sKa[2 * t] = kx; sKa[2 * t + 1] = ky;
    }
    __syncthreads();
    if (t < 32) {
        int h = t >> 3, j = t & 7;
        float num = 0.f, den = 0.f;
        #pragma unroll
        for (int i = 0; i < 16; ++i) {
            float q = g_Q[n * 64 + h * 16 + i];
            num += q * sM[h * 128 + i * 8 + j];
            den += q * sKa[h * 16 + i];
        }
        float e0 = __expf(headwise[0 * KHOPS + 0]);
        float e1 = __expf(headwise[1 * KHOPS + 0]);
        float e2 = __expf(headwise[2 * KHOPS + 0]);
        float e3 = __expf(headwise[3 * KHOPS + 0]);
        float esum = e0 + e1 + e2 + e3;
        float lw = (h == 0 ? e0 : h == 1 ? e1 : h == 2 ? e2 : e3) / esum;
        float gamma = hopwise[1] * lw;
        g_hidden[n * 32 + t] += gamma * num / (den + CSTc);
    }
}

// ---------------- hop 1: full-M gather + attention (no writeback) ----------------
__global__ void hop1_kernel(const __half2* __restrict__ Min, const __half2* __restrict__ Kin,
                            const float* __restrict__ hopwise,
                            const float* __restrict__ headwise) {
    __shared__ float sM[512];
    __shared__ float sK[64];
    int n = blockIdx.x;
    int t = threadIdx.x;                  // 256
    int beg = g_rowptr[n], end = g_rowptr[n + 1];
    float accx = 0.f, accy = 0.f, kx = 0.f, ky = 0.f;
    int e = beg;
    for (; e + 1 < end; e += 2) {
        int s0 = g_src[e], s1 = g_src[e + 1];
        float w0 = g_deginv[s0], w1 = g_deginv[s1];
        float2 m0 = __half22float2(Min[(size_t)s0 * 256 + t]);
        float2 m1 = __half22float2(Min[(size_t)s1 * 256 + t]);
        accx += m0.x * w0 + m1.x * w1;
        accy += m0.y * w0 + m1.y * w1;
        if (t < 32) {
            float2 k0 = __half22float2(Kin[s0 * 32 + t]);
            float2 k1 = __half22float2(Kin[s1 * 32 + t]);
            kx += k0.x * w0 + k1.x * w1;
            ky += k0.y * w0 + k1.y * w1;
        }
    }
    if (e < end) {
        int s0 = g_src[e];
        float w0 = g_deginv[s0];
        float2 m0 = __half22float2(Min[(size_t)s0 * 256 + t]);
        accx += m0.x * w0;
        accy += m0.y * w0;
        if (t < 32) {
            float2 k0 = __half22float2(Kin[s0 * 32 + t]);
            kx += k0.x * w0;
            ky += k0.y * w0;
        }
    }
    sM[2 * t] = accx; sM[2 * t + 1] = accy;
    if (t < 32) { sK[2 * t] = kx; sK[2 * t + 1] = ky; }
    __syncthreads();
    if (t < 32) {
        int h = t >> 3, j = t & 7;
        float num = 0.f, den = 0.f;
        #pragma unroll
        for (int i = 0; i < 16; ++i) {
            float q = g_Q[n * 64 + h * 16 + i];
            num += q * sM[h * 128 + i * 8 + j];
            den += q * sK[h * 16 + i];
        }
        float e0 = __expf(headwise[0 * KHOPS + 1]);
        float e1 = __expf(headwise[1 * KHOPS + 1]);
        float e2 = __expf(headwise[2 * KHOPS + 1]);
        float e3 = __expf(headwise[3 * KHOPS + 1]);
        float esum = e0 + e1 + e2 + e3;
        float lw = (h == 0 ? e0 : h == 1 ? e1 : h == 2 ? e2 : e3) / esum;
        float gamma = hopwise[2] * lw;
        g_hidden[n * 32 + t] += gamma * num / (den + CSTc);
    }
}

// ---------------- output projection + teleport term ----------------
__global__ void final_kernel(const float* __restrict__ Wo, const float* __restrict__ bo,
                             const float* __restrict__ teleport, float* __restrict__ out) {
    int idx = blockIdx.x * blockDim.x + threadIdx.x;  // n*8 + c
    if (idx >= Nn * 8) return;
    int n = idx >> 3, c = idx & 7;
    float acc = bo[c];
    #pragma unroll
    for (int t = 0; t < 32; ++t) acc += g_hidden[n * 32 + t] * Wo[t * 8 + c];
    const float invN = 1.0f / (float)Nn;
    float th = 0.f;
    #pragma unroll
    for (int h = 0; h < 4; ++h) {
        float num = 0.f, den = 0.f;
        #pragma unroll
        for (int i = 0; i < 16; ++i) {
            float q = g_Q[n * 64 + h * 16 + i];
            num += q * g_tM[h * 128 + i * 8 + c];
            den += q * g_tK[h * 16 + i];
        }
        th += (num * invN) / (den * invN + CSTc);
    }
    out[idx] = acc + teleport[0] * th;
}

// ---------------- launch ----------------
extern "C" void kernel_launch(void* const* d_in, const int* in_sizes, int n_in,
                              void* d_out, int out_size) {
    const float* node_feat = (const float*)d_in[0];
    const void*  ei        = d_in[1];
    const float* Wi        = (const float*)d_in[2];
    const float* bi        = (const float*)d_in[3];
    const float* Wq        = (const float*)d_in[4];
    const float* bq        = (const float*)d_in[5];
    const float* Wk        = (const float*)d_in[6];
    const float* bk        = (const float*)d_in[7];
    const float* Wv        = (const float*)d_in[8];
    const float* bv        = (const float*)d_in[9];
    const float* Wo        = (const float*)d_in[10];
    const float* bo        = (const float*)d_in[11];
    const float* hopwise   = (const float*)d_in[12];
    const float* headwise  = (const float*)d_in[13];
    const float* teleport  = (const float*)d_in[14];
    float* out = (float*)d_out;

    __half2* M1p;  cudaGetSymbolAddress((void**)&M1p, g_M1h);
    __half*  Kb16p; cudaGetSymbolAddress((void**)&Kb16p, g_Kb16);

    zero_kernel<<<(Nn + 255) / 256, 256>>>();
    detect_kernel<<<(Ee + 255) / 256, 256>>>((const long long*)ei);
    deg_kernel<<<(Ee + 255) / 256, 256>>>(ei);
    deginv_kernel<<<(Nn + 255) / 256, 256>>>();
    scan_kernel<<<1, 1024>>>();
    fill_kernel<<<(Ee + 255) / 256, 256>>>(ei);

    gemm_x_kernel<<<(Nn + 63) / 64, 256>>>(node_feat, Wi, bi);
    qkv_kernel<<<(Nn * 160 + 255) / 256, 256>>>(Wq, bq, Wk, bk, Wv, bv);
    minit_kernel<<<512, 256>>>(hopwise);

    hop0_kernel<<<Nn, 256>>>(hopwise, headwise);
    hop1_kernel<<<Nn, 256>>>(M1p, (const __half2*)Kb16p, hopwise, headwise);

    final_kernel<<<(Nn * 8 + 255) / 256, 256>>>(Wo, bo, teleport, out);
}

// round 7
// speedup vs baseline: 2.5670x; 1.1115x over previous
#include <cuda_runtime.h>
#include <cuda_fp16.h>
#include <mma.h>
#include <math.h>

using namespace nvcuda;

#define Nn   50000
#define Ee   800000
#define Ff   500
#define HIDD 64
#define KHOPS 2
#define CSTc 1e-5f

// ---------------- device scratch (no allocations allowed) ----------------
__device__ float  g_x[Nn * HIDD];
__device__ float  g_Q[Nn * HIDD];
__device__ float  g_K[Nn * HIDD];
__device__ float  g_V[Nn * 32];
__device__ __half  g_K16[Nn * 64];
__device__ __half  g_V16[Nn * 32];
__device__ __half2 g_M1h[(size_t)Nn * 256];  // M after hop0 (51MB)
__device__ __half  g_Kb16[Nn * 64];
__device__ float  g_hidden[Nn * 32];
__device__ float  g_deginv[Nn];
__device__ int    g_deg[Nn];
__device__ int    g_rowptr[Nn + 1];
__device__ int    g_fill[Nn];
__device__ int    g_src[Ee];
__device__ float  g_tM[512];
__device__ float  g_tK[64];
__device__ int    g_bsum[256];
__device__ int    g_is32 = 0;

// ---------------- dtype detection ----------------
__global__ void detect_kernel(const long long* __restrict__ ei) {
    int e = blockIdx.x * blockDim.x + threadIdx.x;
    if (e >= Ee) return;
    long long v = ei[e];
    if (v < 0 || v >= (long long)Nn) g_is32 = 1;
}

__global__ void zero_kernel() {
    int i = blockIdx.x * blockDim.x + threadIdx.x;
    if (i < Nn) { g_deg[i] = 0; g_fill[i] = 0; }
    if (i < 512) g_tM[i] = 0.f;
    if (i < 64)  g_tK[i] = 0.f;
}

__device__ __forceinline__ int load_edge(const void* ei, int which, int e) {
    if (g_is32) return ((const int*)ei)[which * Ee + e];
    return (int)((const long long*)ei)[which * Ee + e];
}

__global__ void deg_kernel(const void* __restrict__ ei) {
    int e = blockIdx.x * blockDim.x + threadIdx.x;
    if (e >= Ee) return;
    atomicAdd(&g_deg[load_edge(ei, 1, e)], 1);
}

// ---------------- multi-block exclusive scan of g_deg -> g_rowptr ----------------
__global__ void partial_kernel() {       // 196 blocks x 256
    __shared__ int ws[8];
    int t = threadIdx.x, lane = t & 31, w = t >> 5;
    int i = blockIdx.x * 256 + t;
    int v = (i < Nn) ? g_deg[i] : 0;
    int x = v;
    #pragma unroll
    for (int o = 16; o > 0; o >>= 1) x += __shfl_down_sync(0xffffffffu, x, o);
    if (lane == 0) ws[w] = x;
    __syncthreads();
    if (t == 0) {
        int s = 0;
        #pragma unroll
        for (int j = 0; j < 8; ++j) s += ws[j];
        g_bsum[blockIdx.x] = s;
    }
}

__global__ void scanb_kernel() {         // 1 block x 256: exclusive scan of g_bsum
    __shared__ int ws[8];
    int t = threadIdx.x, lane = t & 31, w = t >> 5;
    int v = g_bsum[t];
    int x = v;
    #pragma unroll
    for (int o = 1; o < 32; o <<= 1) {
        int y = __shfl_up_sync(0xffffffffu, x, o);
        if (lane >= o) x += y;
    }
    if (lane == 31) ws[w] = x;
    __syncthreads();
    if (w == 0 && lane < 8) {
        int s = ws[lane];
        #pragma unroll
        for (int o = 1; o < 8; o <<= 1) {
            int y = __shfl_up_sync(0xffu, s, o);
            if (lane >= o) s += y;
        }
        ws[lane] = s;
    }
    __syncthreads();
    int off = (w > 0) ? ws[w - 1] : 0;
    g_bsum[t] = off + x - v;             // exclusive
    if (t == 0) g_rowptr[Nn] = Ee;       // total in-degree == E
}

__global__ void rowptr_kernel() {        // 196 blocks x 256: rescan + deginv
    __shared__ int ws[8];
    int t = threadIdx.x, lane = t & 31, w = t >> 5;
    int i = blockIdx.x * 256 + t;
    int v = (i < Nn) ? g_deg[i] : 0;
    int x = v;
    #pragma unroll
    for (int o = 1; o < 32; o <<= 1) {
        int y = __shfl_up_sync(0xffffffffu, x, o);
        if (lane >= o) x += y;
    }
    if (lane == 31) ws[w] = x;
    __syncthreads();
    if (w == 0 && lane < 8) {
        int s = ws[lane];
        #pragma unroll
        for (int o = 1; o < 8; o <<= 1) {
            int y = __shfl_up_sync(0xffu, s, o);
            if (lane >= o) s += y;
        }
        ws[lane] = s;
    }
    __syncthreads();
    int off = (w > 0) ? ws[w - 1] : 0;
    if (i < Nn) {
        g_rowptr[i] = g_bsum[blockIdx.x] + off + x - v;
        g_deginv[i] = v > 0 ? 1.0f / (float)v : 0.0f;
    }
}

__global__ void fill_kernel(const void* __restrict__ ei) {
    int e = blockIdx.x * blockDim.x + threadIdx.x;
    if (e >= Ee) return;
    int r = load_edge(ei, 0, e);
    int c = load_edge(ei, 1, e);
    int pos = g_rowptr[c] + atomicAdd(&g_fill[c], 1);
    g_src[pos] = r;
}

// ---------------- x = relu(A @ Wi + bi) via wmma fp16 ----------------
// block: 256 threads (8 warps), tile 128 rows x 64 cols, K chunks of 64 (padded to 512)
__global__ void gemm_x_kernel(const float* __restrict__ A,
                              const float* __restrict__ Wi,
                              const float* __restrict__ bi) {
    __shared__ __align__(16) char smemBuf[34816];
    __half (*sA)[72] = (__half(*)[72])smemBuf;                    // 128 x 72 (18432 B)
    __half (*sW)[72] = (__half(*)[72])(smemBuf + 18432);          // 64 x 72  (9216 B)
    float (*sC)[68]  = (float(*)[68])smemBuf;                     // 128 x 68 (34816 B)

    int t = threadIdx.x;
    int warp = t >> 5;
    int r0 = blockIdx.x * 128;

    wmma::fragment<wmma::accumulator, 16, 16, 16, float> c[4];
    #pragma unroll
    for (int nb = 0; nb < 4; ++nb) wmma::fill_fragment(c[nb], 0.0f);

    for (int kc = 0; kc < 512; kc += 64) {
        // stage A tile (fp32 -> fp16), 128x64
        for (int i = t; i < 128 * 32; i += 256) {
            int r  = i >> 5;
            int c2 = (i & 31) * 2;
            int gr = r0 + r, gk = kc + c2;
            float2 v = make_float2(0.f, 0.f);
            if (gr < Nn) {
                if (gk + 1 < Ff)      v = *(const float2*)&A[(size_t)gr * Ff + gk];
                else if (gk < Ff)     v.x = A[(size_t)gr * Ff + gk];
            }
            *(__half2*)&sA[r][c2] = __floats2half2_rn(v.x, v.y);
        }
        // stage W tile, 64x64
        for (int i = t; i < 64 * 32; i += 256) {
            int kk = i >> 5;
            int c2 = (i & 31) * 2;
            int gk = kc + kk;
            float2 v = make_float2(0.f, 0.f);
            if (gk < Ff) v = *(const float2*)&Wi[gk * 64 + c2];
            *(__half2*)&sW[kk][c2] = __floats2half2_rn(v.x, v.y);
        }
        __syncthreads();
        #pragma unroll
        for (int ks = 0; ks < 64; ks += 16) {
            wmma::fragment<wmma::matrix_a, 16, 16, 16, __half, wmma::row_major> a;
            wmma::load_matrix_sync(a, &sA[warp * 16][ks], 72);
            #pragma unroll
            for (int nb = 0; nb < 4; ++nb) {
                wmma::fragment<wmma::matrix_b, 16, 16, 16, __half, wmma::row_major> b;
                wmma::load_matrix_sync(b, &sW[ks][nb * 16], 72);
                wmma::mma_sync(c[nb], a, b, c[nb]);
            }
        }
        __syncthreads();
    }
    // epilogue: frags -> smem fp32 -> bias+relu -> gmem
    #pragma unroll
    for (int nb = 0; nb < 4; ++nb)
        wmma::store_matrix_sync(&sC[warp * 16][nb * 16], c[nb], 68, wmma::mem_row_major);
    __syncthreads();
    for (int i = t; i < 128 * 64; i += 256) {
        int r = i >> 6, cc = i & 63;
        int gr = r0 + r;
        if (gr < Nn) g_x[gr * 64 + cc] = fmaxf(sC[r][cc] + bi[cc], 0.f);
    }
}

// ---------------- Q/K/V projections ----------------
__global__ void qkv_kernel(const float* __restrict__ Wq, const float* __restrict__ bq,
                           const float* __restrict__ Wk, const float* __restrict__ bk,
                           const float* __restrict__ Wv, const float* __restrict__ bv) {
    int idx = blockIdx.x * blockDim.x + threadIdx.x;
    if (idx >= Nn * 160) return;
    int n = idx / 160;
    int oc = idx - n * 160;
    const float* xr = g_x + n * HIDD;
    if (oc < 64) {
        float acc = bq[oc];
        #pragma unroll 8
        for (int k = 0; k < HIDD; ++k) acc += xr[k] * Wq[k * 64 + oc];
        g_Q[n * 64 + oc] = acc > 0.f ? 1.f + acc : __expf(acc);
    } else if (oc < 128) {
        int c = oc - 64;
        float acc = bk[c];
        #pragma unroll 8
        for (int k = 0; k < HIDD; ++k) acc += xr[k] * Wk[k * 64 + c];
        g_K[n * 64 + c] = acc > 0.f ? 1.f + acc : __expf(acc);
    } else {
        int c = oc - 128;
        float acc = bv[c];
        #pragma unroll 8
        for (int k = 0; k < HIDD; ++k) acc += xr[k] * Wv[k * 32 + c];
        g_V[n * 32 + c] = acc;
    }
}

// ---------------- teleport sums ; hidden init ; fp16 copies of K,V ----------------
__global__ void minit_kernel(const float* __restrict__ hopwise) {
    int t = threadIdx.x;
    int npb = (Nn + gridDim.x - 1) / gridDim.x;
    int n0 = blockIdx.x * npb;
    int n1 = min(n0 + npb, Nn);
    int kidx  = t >> 2;
    int vbase = ((t >> 6) << 3) | ((2 * t) & 7);
    float h0 = hopwise[0];
    float tm0 = 0.f, tm1 = 0.f, tk = 0.f;
    for (int n = n0; n < n1; ++n) {
        float kv = g_K[n * 64 + kidx];
        float2 vv = *(const float2*)&g_V[n * 32 + vbase];
        tm0 += kv * vv.x; tm1 += kv * vv.y;
        if (t < 64) {
            float k = g_K[n * 64 + t];
            tk += k;
            g_K16[n * 64 + t] = __float2half_rn(k);
        }
        if (t < 32) {
            float v = g_V[n * 32 + t];
            g_hidden[n * 32 + t] = v * h0;
            g_V16[n * 32 + t] = __float2half_rn(v);
        }
    }
    atomicAdd(&g_tM[2 * t], tm0);
    atomicAdd(&g_tM[2 * t + 1], tm1);
    if (t < 64) atomicAdd(&g_tK[t], tk);
}

// ---------------- hop 0: on-the-fly outer-product propagate + attention ----------------
#define CH 16
__global__ void hop0_kernel(const float* __restrict__ hopwise,
                            const float* __restrict__ headwise) {
    __shared__ __half2 sKe[CH][32];
    __shared__ __half2 sVe[CH][16];
    __shared__ float   swv[CH];
    __shared__ float   sM[512];
    __shared__ float   sKa[64];
    int n = blockIdx.x;
    int t = threadIdx.x;
    int beg = g_rowptr[n], end = g_rowptr[n + 1];
    int kidx = t >> 2;
    int vh2  = ((t >> 6) << 2) | (t & 3);
    float accx = 0.f, accy = 0.f, kx = 0.f, ky = 0.f;
    const __half2* K2 = (const __half2*)g_K16;
    const __half2* V2 = (const __half2*)g_V16;
    for (int c0 = beg; c0 < end; c0 += CH) {
        int ne = min(CH, end - c0);
        for (int idx = t; idx < ne * 48; idx += 256) {
            int e = idx / 48, off = idx - e * 48;
            int s = g_src[c0 + e];
            if (off < 32) sKe[e][off] = K2[s * 32 + off];
            else          sVe[e][off - 32] = V2[s * 16 + (off - 32)];
        }
        if (t < ne) swv[t] = g_deginv[g_src[c0 + t]];
        __syncthreads();
        for (int e = 0; e < ne; ++e) {
            float w = swv[e];
            float k = __half2float(((const __half*)sKe[e])[kidx]);
            float2 v = __half22float2(sVe[e][vh2]);
            float wk = w * k;
            accx += wk * v.x;
            accy += wk * v.y;
            if (t < 32) {
                float2 kk = __half22float2(sKe[e][t]);
                kx += w * kk.x;
                ky += w * kk.y;
            }
        }
        __syncthreads();
    }
    g_M1h[(size_t)n * 256 + t] = __floats2half2_rn(accx, accy);
    sM[2 * t] = accx; sM[2 * t + 1] = accy;
    if (t < 32) {
        ((__half2*)g_Kb16)[n * 32 + t] = __floats2half2_rn(kx, ky);
        sKa[2 * t] = kx; sKa[2 * t + 1] = ky;
    }
    __syncthreads();
    if (t < 32) {
        int h = t >> 3, j = t & 7;
        float num = 0.f, den = 0.f;
        #pragma unroll
        for (int i = 0; i < 16; ++i) {
            float q = g_Q[n * 64 + h * 16 + i];
            num += q * sM[h * 128 + i * 8 + j];
            den += q * sKa[h * 16 + i];
        }
        float e0 = __expf(headwise[0 * KHOPS + 0]);
        float e1 = __expf(headwise[1 * KHOPS + 0]);
        float e2 = __expf(headwise[2 * KHOPS + 0]);
        float e3 = __expf(headwise[3 * KHOPS + 0]);
        float esum = e0 + e1 + e2 + e3;
        float lw = (h == 0 ? e0 : h == 1 ? e1 : h == 2 ? e2 : e3) / esum;
        float gamma = hopwise[1] * lw;
        g_hidden[n * 32 + t] += gamma * num / (den + CSTc);
    }
}

// ---------------- hop 1: full-M gather + attention (no writeback) ----------------
__global__ void hop1_kernel(const __half2* __restrict__ Min, const __half2* __restrict__ Kin,
                            const float* __restrict__ hopwise,
                            const float* __restrict__ headwise) {
    __shared__ float sM[512];
    __shared__ float sK[64];
    int n = blockIdx.x;
    int t = threadIdx.x;
    int beg = g_rowptr[n], end = g_rowptr[n + 1];
    float accx = 0.f, accy = 0.f, kx = 0.f, ky = 0.f;
    int e = beg;
    for (; e + 1 < end; e += 2) {
        int s0 = g_src[e], s1 = g_src[e + 1];
        float w0 = g_deginv[s0], w1 = g_deginv[s1];
        float2 m0 = __half22float2(Min[(size_t)s0 * 256 + t]);
        float2 m1 = __half22float2(Min[(size_t)s1 * 256 + t]);
        accx += m0.x * w0 + m1.x * w1;
        accy += m0.y * w0 + m1.y * w1;
        if (t < 32) {
            float2 k0 = __half22float2(Kin[s0 * 32 + t]);
            float2 k1 = __half22float2(Kin[s1 * 32 + t]);
            kx += k0.x * w0 + k1.x * w1;
            ky += k0.y * w0 + k1.y * w1;
        }
    }
    if (e < end) {
        int s0 = g_src[e];
        float w0 = g_deginv[s0];
        float2 m0 = __half22float2(Min[(size_t)s0 * 256 + t]);
        accx += m0.x * w0;
        accy += m0.y * w0;
        if (t < 32) {
            float2 k0 = __half22float2(Kin[s0 * 32 + t]);
            kx += k0.x * w0;
            ky += k0.y * w0;
        }
    }
    sM[2 * t] = accx; sM[2 * t + 1] = accy;
    if (t < 32) { sK[2 * t] = kx; sK[2 * t + 1] = ky; }
    __syncthreads();
    if (t < 32) {
        int h = t >> 3, j = t & 7;
        float num = 0.f, den = 0.f;
        #pragma unroll
        for (int i = 0; i < 16; ++i) {
            float q = g_Q[n * 64 + h * 16 + i];
            num += q * sM[h * 128 + i * 8 + j];
            den += q * sK[h * 16 + i];
        }
        float e0 = __expf(headwise[0 * KHOPS + 1]);
        float e1 = __expf(headwise[1 * KHOPS + 1]);
        float e2 = __expf(headwise[2 * KHOPS + 1]);
        float e3 = __expf(headwise[3 * KHOPS + 1]);
        float esum = e0 + e1 + e2 + e3;
        float lw = (h == 0 ? e0 : h == 1 ? e1 : h == 2 ? e2 : e3) / esum;
        float gamma = hopwise[2] * lw;
        g_hidden[n * 32 + t] += gamma * num / (den + CSTc);
    }
}

// ---------------- output projection + teleport term ----------------
__global__ void final_kernel(const float* __restrict__ Wo, const float* __restrict__ bo,
                             const float* __restrict__ teleport, float* __restrict__ out) {
    int idx = blockIdx.x * blockDim.x + threadIdx.x;
    if (idx >= Nn * 8) return;
    int n = idx >> 3, c = idx & 7;
    float acc = bo[c];
    #pragma unroll
    for (int t = 0; t < 32; ++t) acc += g_hidden[n * 32 + t] * Wo[t * 8 + c];
    const float invN = 1.0f / (float)Nn;
    float th = 0.f;
    #pragma unroll
    for (int h = 0; h < 4; ++h) {
        float num = 0.f, den = 0.f;
        #pragma unroll
        for (int i = 0; i < 16; ++i) {
            float q = g_Q[n * 64 + h * 16 + i];
            num += q * g_tM[h * 128 + i * 8 + c];
            den += q * g_tK[h * 16 + i];
        }
        th += (num * invN) / (den * invN + CSTc);
    }
    out[idx] = acc + teleport[0] * th;
}

// ---------------- launch ----------------
extern "C" void kernel_launch(void* const* d_in, const int* in_sizes, int n_in,
                              void* d_out, int out_size) {
    const float* node_feat = (const float*)d_in[0];
    const void*  ei        = d_in[1];
    const float* Wi        = (const float*)d_in[2];
    const float* bi        = (const float*)d_in[3];
    const float* Wq        = (const float*)d_in[4];
    const float* bq        = (const float*)d_in[5];
    const float* Wk        = (const float*)d_in[6];
    const float* bk        = (const float*)d_in[7];
    const float* Wv        = (const float*)d_in[8];
    const float* bv        = (const float*)d_in[9];
    const float* Wo        = (const float*)d_in[10];
    const float* bo        = (const float*)d_in[11];
    const float* hopwise   = (const float*)d_in[12];
    const float* headwise  = (const float*)d_in[13];
    const float* teleport  = (const float*)d_in[14];
    float* out = (float*)d_out;

    __half2* M1p;  cudaGetSymbolAddress((void**)&M1p, g_M1h);
    __half*  Kb16p; cudaGetSymbolAddress((void**)&Kb16p, g_Kb16);

    zero_kernel<<<(Nn + 255) / 256, 256>>>();
    detect_kernel<<<(Ee + 255) / 256, 256>>>((const long long*)ei);
    deg_kernel<<<(Ee + 255) / 256, 256>>>(ei);
    partial_kernel<<<196, 256>>>();
    scanb_kernel<<<1, 256>>>();
    rowptr_kernel<<<196, 256>>>();
    fill_kernel<<<(Ee + 255) / 256, 256>>>(ei);

    gemm_x_kernel<<<(Nn + 127) / 128, 256>>>(node_feat, Wi, bi);
    qkv_kernel<<<(Nn * 160 + 255) / 256, 256>>>(Wq, bq, Wk, bk, Wv, bv);
    minit_kernel<<<512, 256>>>(hopwise);

    hop0_kernel<<<Nn, 256>>>(hopwise, headwise);
    hop1_kernel<<<Nn, 256>>>(M1p, (const __half2*)Kb16p, hopwise, headwise);

    final_kernel<<<(Nn * 8 + 255) / 256, 256>>>(Wo, bo, teleport, out);
}